// round 16
// baseline (speedup 1.0000x reference)
#include <cuda_runtime.h>
#include <cuda_bf16.h>
#include <mma.h>

using namespace nvcuda;
typedef __nv_bfloat16 bf16;

#define NROWS 32768
#define DOBS 256
#define HDIM 512
#define NA 32
#define NROLES 6

// ---------------- cp.async helpers ----------------------------------------
__device__ __forceinline__ void cp16(void* sdst, const void* gsrc) {
    unsigned int d = (unsigned int)__cvta_generic_to_shared(sdst);
    asm volatile("cp.async.cg.shared.global [%0], [%1], 16;" :: "r"(d), "l"(gsrc));
}
#define CP_COMMIT() asm volatile("cp.async.commit_group;")
#define CP_WAIT(n)  asm volatile("cp.async.wait_group %0;" :: "n"(n))

// ---------------- scratch (device globals; no allocation allowed) ----------
__device__ __align__(256) bf16  g_obsnh[NROWS * DOBS];
__device__ __align__(256) bf16  g_obsnl[NROWS * DOBS];
__device__ __align__(256) bf16  g_w0h[DOBS * HDIM], g_w0l[DOBS * HDIM];
__device__ __align__(256) bf16  g_w1h[HDIM * HDIM], g_w1l[HDIM * HDIM];
__device__ __align__(256) bf16  g_wr0h[NROLES * DOBS * 128], g_wr0l[NROLES * DOBS * 128];
__device__ __align__(256) bf16  g_wr1h[NROLES * 128 * HDIM], g_wr1l[NROLES * 128 * HDIM];
__device__ __align__(256) bf16  g_wh0h[NROLES * HDIM * 64], g_wh0l[NROLES * HDIM * 64];
__device__ __align__(256) float g_pre[NROWS * HDIM];      // relu(x@W0+b0)
__device__ __align__(256) float g_pre2[NROWS * HDIM];     // relu(e0@W1+b1)
__device__ __align__(256) float g_partS[NROWS * 8], g_partQ[NROWS * 8];
__device__ __align__(256) float g_mean[NROWS], g_rstd[NROWS];
__device__ __align__(256) bf16  g_e1h[NROWS * HDIM], g_e1l[NROWS * HDIM];
__device__ __align__(256) bf16  g_r0h[NROWS * 128], g_r0l[NROWS * 128];
__device__ int   g_rows[NROLES * NROWS];
__device__ int   g_cnt[NROLES];

// ---------------- small kernels -------------------------------------------
__global__ void k_copy4(const float4* __restrict__ src, float4* __restrict__ dst, int n4) {
    int i = blockIdx.x * blockDim.x + threadIdx.x;
    if (i < n4) dst[i] = src[i];
}

__global__ void k_zero_cnt() {
    if (threadIdx.x < NROLES) g_cnt[threadIdx.x] = 0;
}

// warp-aggregated bucketing
__global__ void k_bucket(const int* __restrict__ role_ids) {
    int i = blockIdx.x * blockDim.x + threadIdx.x;
    int r = role_ids[i];
    unsigned mask = __match_any_sync(0xffffffffu, r);
    int lane = threadIdx.x & 31;
    int leader = __ffs(mask) - 1;
    int prefix = __popc(mask & ((1u << lane) - 1));
    int base = 0;
    if (lane == leader) base = atomicAdd(&g_cnt[r], __popc(mask));
    base = __shfl_sync(0xffffffffu, base, leader);
    g_rows[r * NROWS + base + prefix] = i;
}

// Fused split of all 5 weight tensors
#define N_W0  (DOBS * HDIM)
#define N_W1  (HDIM * HDIM)
#define N_WR0 (NROLES * DOBS * 128)
#define N_WR1 (NROLES * 128 * HDIM)
#define N_WH0 (NROLES * HDIM * 64)
#define N_SPLIT_TOT (N_W0 + N_W1 + N_WR0 + N_WR1 + N_WH0)
__global__ void k_split_all(const float* __restrict__ W0, const float* __restrict__ W1,
                            const float* __restrict__ Wr0, const float* __restrict__ Wr1,
                            const float* __restrict__ Wh0) {
    int i = blockIdx.x * blockDim.x + threadIdx.x;
    if (i >= N_SPLIT_TOT) return;
    const float* src; bf16 *dh, *dl; int off;
    if (i < N_W0) { src = W0; dh = g_w0h; dl = g_w0l; off = i; }
    else if (i < N_W0 + N_W1) { src = W1; dh = g_w1h; dl = g_w1l; off = i - N_W0; }
    else if (i < N_W0 + N_W1 + N_WR0) { src = Wr0; dh = g_wr0h; dl = g_wr0l; off = i - N_W0 - N_W1; }
    else if (i < N_W0 + N_W1 + N_WR0 + N_WR1) { src = Wr1; dh = g_wr1h; dl = g_wr1l; off = i - N_W0 - N_W1 - N_WR0; }
    else { src = Wh0; dh = g_wh0h; dl = g_wh0l; off = i - N_W0 - N_W1 - N_WR0 - N_WR1; }
    float v = src[off];
    bf16 h = __float2bfloat16(v);
    dh[off] = h;
    dl[off] = __float2bfloat16(v - __bfloat162float(h));
}

// LayerNorm over obs (256), warp per row; writes bf16 hi/lo
__global__ void k_ln_obs(const float* __restrict__ obs, const float* __restrict__ sc,
                         const float* __restrict__ bi) {
    int warp = threadIdx.x >> 5, lane = threadIdx.x & 31;
    int row = blockIdx.x * 8 + warp;
    const float* src = obs + (size_t)row * DOBS;
    float x[8]; float s = 0.f, q = 0.f;
#pragma unroll
    for (int j = 0; j < 8; j++) { x[j] = src[lane + 32 * j]; s += x[j]; q += x[j] * x[j]; }
#pragma unroll
    for (int o = 16; o > 0; o >>= 1) {
        s += __shfl_xor_sync(0xffffffffu, s, o);
        q += __shfl_xor_sync(0xffffffffu, q, o);
    }
    float m = s * (1.f / DOBS);
    float v = q * (1.f / DOBS) - m * m;
    float rs = rsqrtf(v + 1e-5f);
#pragma unroll
    for (int j = 0; j < 8; j++) {
        int d = lane + 32 * j;
        float y = (x[j] - m) * rs * sc[d] + bi[d];
        size_t o = (size_t)row * DOBS + d;
        bf16 h = __float2bfloat16(y);
        g_obsnh[o] = h;
        g_obsnl[o] = __float2bfloat16(y - __bfloat162float(h));
    }
}

// reduce 8 per-slice partials -> mean/rstd per row
__global__ void k_stats() {
    int r = blockIdx.x * blockDim.x + threadIdx.x;
    float s = 0.f, q = 0.f;
#pragma unroll
    for (int i = 0; i < 8; i++) { s += g_partS[r * 8 + i]; q += g_partQ[r * 8 + i]; }
    float m = s * (1.f / HDIM);
    float var = q * (1.f / HDIM) - m * m;
    g_mean[r] = m;
    g_rstd[r] = rsqrtf(var + 1e-5f);
}

// ---------------- dense bf16x3 TC GEMM + relu/bias + LN-partials ----------
// out = relu(A@W + bias) (fp32), plus per-(row, col-slice) sum/sumsq partials.
#define ASTR 40
#define BSTR 136
#define A_SZ (128 * ASTR * 2)
#define B_SZ (32 * BSTR * 2)
#define STAGE (2 * A_SZ + 2 * B_SZ)
#define GEMM_SMEM (2 * STAGE)

// shared epilogue: stage fragments, relu+bias, write pre + LN partials
#define GEMM_EPILOGUE(accv)                                                     \
    {                                                                           \
        float* CstW = (float*)dsm + w * (16 * 20);                              \
        const int lr = lane & 15, lc = (lane >> 4) * 8;                         \
        float rowS[2] = {0.f, 0.f}, rowQ[2] = {0.f, 0.f};                       \
        _Pragma("unroll")                                                       \
        for (int mi = 0; mi < 2; mi++) {                                        \
            _Pragma("unroll")                                                   \
            for (int ni = 0; ni < 4; ni++) {                                    \
                wmma::store_matrix_sync(CstW, accv[mi][ni], 20, wmma::mem_row_major); \
                __syncwarp();                                                   \
                int colb = col0 + wn * 64 + ni * 16 + lc;                       \
                float v[8];                                                     \
                _Pragma("unroll")                                               \
                for (int j = 0; j < 8; j++) {                                   \
                    v[j] = fmaxf(CstW[lr * 20 + lc + j] + bias[colb + j], 0.f); \
                    rowS[mi] += v[j]; rowQ[mi] += v[j] * v[j];                  \
                }                                                               \
                float* dst = &out[(size_t)(row0 + wm * 32 + mi * 16 + lr) * HDIM + colb]; \
                *(float4*)dst = make_float4(v[0], v[1], v[2], v[3]);            \
                *(float4*)(dst + 4) = make_float4(v[4], v[5], v[6], v[7]);      \
                __syncwarp();                                                   \
            }                                                                   \
        }                                                                       \
        _Pragma("unroll")                                                       \
        for (int mi = 0; mi < 2; mi++) {                                        \
            float s = rowS[mi] + __shfl_xor_sync(0xffffffffu, rowS[mi], 16);    \
            float q = rowQ[mi] + __shfl_xor_sync(0xffffffffu, rowQ[mi], 16);    \
            if (lane < 16) {                                                    \
                int rg = row0 + wm * 32 + mi * 16 + lr;                         \
                int cs = blockIdx.y * 2 + wn;                                   \
                g_partS[rg * 8 + cs] = s;                                       \
                g_partQ[rg * 8 + cs] = q;                                       \
            }                                                                   \
        }                                                                       \
    }

// variant A: A given as bf16 hi/lo (layer 0)
__global__ __launch_bounds__(256) void k_gemm_st(
    const bf16* __restrict__ Ah, const bf16* __restrict__ Al,
    const bf16* __restrict__ Wh, const bf16* __restrict__ Wl,
    const float* __restrict__ bias, float* __restrict__ out, int K)
{
    extern __shared__ __align__(16) char dsm[];
    const int t = threadIdx.x;
    const int w = t >> 5, lane = t & 31;
    const int wm = w & 3, wn = w >> 2;
    const int row0 = blockIdx.x * 128, col0 = blockIdx.y * 128;

    wmma::fragment<wmma::accumulator, 16, 16, 16, float> acc[2][4];
#pragma unroll
    for (int i = 0; i < 2; i++)
#pragma unroll
        for (int j = 0; j < 4; j++) wmma::fill_fragment(acc[i][j], 0.f);

    const int ar = t >> 2, ac8 = (t & 3) * 8;
    const int br = t >> 4, bc8 = (t & 15) * 8;
    const int nk = K / 32;

    auto prefetch = [&](int s, int k0) {
        bf16* ah = (bf16*)(dsm + s * STAGE);
        bf16* al = (bf16*)(dsm + s * STAGE + A_SZ);
        bf16* bh = (bf16*)(dsm + s * STAGE + 2 * A_SZ);
        bf16* bl = (bf16*)(dsm + s * STAGE + 2 * A_SZ + B_SZ);
        cp16(&ah[ar * ASTR + ac8],        &Ah[(size_t)(row0 + ar) * K + k0 + ac8]);
        cp16(&ah[(ar + 64) * ASTR + ac8], &Ah[(size_t)(row0 + ar + 64) * K + k0 + ac8]);
        cp16(&al[ar * ASTR + ac8],        &Al[(size_t)(row0 + ar) * K + k0 + ac8]);
        cp16(&al[(ar + 64) * ASTR + ac8], &Al[(size_t)(row0 + ar + 64) * K + k0 + ac8]);
        cp16(&bh[br * BSTR + bc8],        &Wh[(size_t)(k0 + br) * HDIM + col0 + bc8]);
        cp16(&bh[(br + 16) * BSTR + bc8], &Wh[(size_t)(k0 + br + 16) * HDIM + col0 + bc8]);
        cp16(&bl[br * BSTR + bc8],        &Wl[(size_t)(k0 + br) * HDIM + col0 + bc8]);
        cp16(&bl[(br + 16) * BSTR + bc8], &Wl[(size_t)(k0 + br + 16) * HDIM + col0 + bc8]);
    };

    prefetch(0, 0);
    CP_COMMIT();
    for (int kt = 0; kt < nk; kt++) {
        int s = kt & 1;
        if (kt + 1 < nk) {
            prefetch((kt + 1) & 1, (kt + 1) * 32);
            CP_COMMIT();
            CP_WAIT(1);
        } else {
            CP_WAIT(0);
        }
        __syncthreads();
        bf16* ah = (bf16*)(dsm + s * STAGE);
        bf16* al = (bf16*)(dsm + s * STAGE + A_SZ);
        bf16* bh = (bf16*)(dsm + s * STAGE + 2 * A_SZ);
        bf16* bl = (bf16*)(dsm + s * STAGE + 2 * A_SZ + B_SZ);
#pragma unroll
        for (int ks = 0; ks < 2; ks++) {
            wmma::fragment<wmma::matrix_a, 16, 16, 16, bf16, wmma::row_major> fah[2], fal[2];
#pragma unroll
            for (int mi = 0; mi < 2; mi++) {
                wmma::load_matrix_sync(fah[mi], &ah[(wm * 32 + mi * 16) * ASTR + ks * 16], ASTR);
                wmma::load_matrix_sync(fal[mi], &al[(wm * 32 + mi * 16) * ASTR + ks * 16], ASTR);
            }
#pragma unroll
            for (int ni = 0; ni < 4; ni++) {
                wmma::fragment<wmma::matrix_b, 16, 16, 16, bf16, wmma::row_major> fbh, fbl;
                wmma::load_matrix_sync(fbh, &bh[ks * 16 * BSTR + wn * 64 + ni * 16], BSTR);
                wmma::load_matrix_sync(fbl, &bl[ks * 16 * BSTR + wn * 64 + ni * 16], BSTR);
#pragma unroll
                for (int mi = 0; mi < 2; mi++) {
                    wmma::mma_sync(acc[mi][ni], fah[mi], fbh, acc[mi][ni]);
                    wmma::mma_sync(acc[mi][ni], fah[mi], fbl, acc[mi][ni]);
                    wmma::mma_sync(acc[mi][ni], fal[mi], fbh, acc[mi][ni]);
                }
            }
        }
        __syncthreads();
    }
    GEMM_EPILOGUE(acc)
}

// variant B: A loaded from fp32 'pre' with LN applied on the fly (layer 1)
__global__ __launch_bounds__(256) void k_gemm_lnA_st(
    const float* __restrict__ preA, const float* __restrict__ lnS,
    const float* __restrict__ lnB,
    const bf16* __restrict__ Wh, const bf16* __restrict__ Wl,
    const float* __restrict__ bias, float* __restrict__ out, int K)
{
    extern __shared__ __align__(16) char dsm[];
    const int t = threadIdx.x;
    const int w = t >> 5, lane = t & 31;
    const int wm = w & 3, wn = w >> 2;
    const int row0 = blockIdx.x * 128, col0 = blockIdx.y * 128;

    wmma::fragment<wmma::accumulator, 16, 16, 16, float> acc[2][4];
#pragma unroll
    for (int i = 0; i < 2; i++)
#pragma unroll
        for (int j = 0; j < 4; j++) wmma::fill_fragment(acc[i][j], 0.f);

    const int ar = t >> 2, ac8 = (t & 3) * 8;
    const int br = t >> 4, bc8 = (t & 15) * 8;
    const int nk = K / 32;

    const float mA0 = g_mean[row0 + ar],      rA0 = g_rstd[row0 + ar];
    const float mA1 = g_mean[row0 + ar + 64], rA1 = g_rstd[row0 + ar + 64];

    float4 a00, a01, a10, a11, ls0, ls1, lb0, lb1;
    auto loadA = [&](int k0) {
        const float* r0p = &preA[(size_t)(row0 + ar) * K + k0 + ac8];
        const float* r1p = &preA[(size_t)(row0 + ar + 64) * K + k0 + ac8];
        a00 = *(const float4*)r0p;       a01 = *(const float4*)(r0p + 4);
        a10 = *(const float4*)r1p;       a11 = *(const float4*)(r1p + 4);
        ls0 = *(const float4*)&lnS[k0 + ac8]; ls1 = *(const float4*)&lnS[k0 + ac8 + 4];
        lb0 = *(const float4*)&lnB[k0 + ac8]; lb1 = *(const float4*)&lnB[k0 + ac8 + 4];
    };
    auto storeA = [&](int s) {
        bf16* ah = (bf16*)(dsm + s * STAGE);
        bf16* al = (bf16*)(dsm + s * STAGE + A_SZ);
        float va[8] = {a00.x, a00.y, a00.z, a00.w, a01.x, a01.y, a01.z, a01.w};
        float vb[8] = {a10.x, a10.y, a10.z, a10.w, a11.x, a11.y, a11.z, a11.w};
        float gs[8] = {ls0.x, ls0.y, ls0.z, ls0.w, ls1.x, ls1.y, ls1.z, ls1.w};
        float gb[8] = {lb0.x, lb0.y, lb0.z, lb0.w, lb1.x, lb1.y, lb1.z, lb1.w};
        bf16 h0[8], l0[8], h1[8], l1[8];
#pragma unroll
        for (int j = 0; j < 8; j++) {
            float y0 = (va[j] - mA0) * rA0 * gs[j] + gb[j];
            bf16 hh = __float2bfloat16(y0);
            h0[j] = hh; l0[j] = __float2bfloat16(y0 - __bfloat162float(hh));
            float y1 = (vb[j] - mA1) * rA1 * gs[j] + gb[j];
            bf16 hk = __float2bfloat16(y1);
            h1[j] = hk; l1[j] = __float2bfloat16(y1 - __bfloat162float(hk));
        }
        *(uint4*)&ah[ar * ASTR + ac8]        = *(uint4*)h0;
        *(uint4*)&al[ar * ASTR + ac8]        = *(uint4*)l0;
        *(uint4*)&ah[(ar + 64) * ASTR + ac8] = *(uint4*)h1;
        *(uint4*)&al[(ar + 64) * ASTR + ac8] = *(uint4*)l1;
    };
    auto prefetchB = [&](int s, int k0) {
        bf16* bh = (bf16*)(dsm + s * STAGE + 2 * A_SZ);
        bf16* bl = (bf16*)(dsm + s * STAGE + 2 * A_SZ + B_SZ);
        cp16(&bh[br * BSTR + bc8],        &Wh[(size_t)(k0 + br) * HDIM + col0 + bc8]);
        cp16(&bh[(br + 16) * BSTR + bc8], &Wh[(size_t)(k0 + br + 16) * HDIM + col0 + bc8]);
        cp16(&bl[br * BSTR + bc8],        &Wl[(size_t)(k0 + br) * HDIM + col0 + bc8]);
        cp16(&bl[(br + 16) * BSTR + bc8], &Wl[(size_t)(k0 + br + 16) * HDIM + col0 + bc8]);
    };

    loadA(0);
    prefetchB(0, 0);
    CP_COMMIT();
    storeA(0);
    for (int kt = 0; kt < nk; kt++) {
        int s = kt & 1;
        if (kt + 1 < nk) {
            loadA((kt + 1) * 32);            // LDG early; consumed after mainloop
            prefetchB(s ^ 1, (kt + 1) * 32);
            CP_COMMIT();
            CP_WAIT(1);
        } else {
            CP_WAIT(0);
        }
        __syncthreads();
        bf16* ah = (bf16*)(dsm + s * STAGE);
        bf16* al = (bf16*)(dsm + s * STAGE + A_SZ);
        bf16* bh = (bf16*)(dsm + s * STAGE + 2 * A_SZ);
        bf16* bl = (bf16*)(dsm + s * STAGE + 2 * A_SZ + B_SZ);
#pragma unroll
        for (int ks = 0; ks < 2; ks++) {
            wmma::fragment<wmma::matrix_a, 16, 16, 16, bf16, wmma::row_major> fah[2], fal[2];
#pragma unroll
            for (int mi = 0; mi < 2; mi++) {
                wmma::load_matrix_sync(fah[mi], &ah[(wm * 32 + mi * 16) * ASTR + ks * 16], ASTR);
                wmma::load_matrix_sync(fal[mi], &al[(wm * 32 + mi * 16) * ASTR + ks * 16], ASTR);
            }
#pragma unroll
            for (int ni = 0; ni < 4; ni++) {
                wmma::fragment<wmma::matrix_b, 16, 16, 16, bf16, wmma::row_major> fbh, fbl;
                wmma::load_matrix_sync(fbh, &bh[ks * 16 * BSTR + wn * 64 + ni * 16], BSTR);
                wmma::load_matrix_sync(fbl, &bl[ks * 16 * BSTR + wn * 64 + ni * 16], BSTR);
#pragma unroll
                for (int mi = 0; mi < 2; mi++) {
                    wmma::mma_sync(acc[mi][ni], fah[mi], fbh, acc[mi][ni]);
                    wmma::mma_sync(acc[mi][ni], fah[mi], fbl, acc[mi][ni]);
                    wmma::mma_sync(acc[mi][ni], fal[mi], fbh, acc[mi][ni]);
                }
            }
        }
        if (kt + 1 < nk) storeA(s ^ 1);      // writes NEXT buffer (no hazard)
        __syncthreads();
    }
    GEMM_EPILOGUE(acc)
}

// ---------------- route1 TC: r0 = relu(obsn @ Wr0[role] + br0) ------------
__global__ __launch_bounds__(256) void k_route1_tc(const float* __restrict__ br0)
{
    const int role = blockIdx.y;
    const int cnt = g_cnt[role];
    const int t0 = blockIdx.x * 128;
    if (t0 >= cnt) return;
    __shared__ __align__(16) bf16 Ash[128][ASTR], Asl[128][ASTR];
    __shared__ __align__(16) bf16 Bsh[32][BSTR], Bsl[32][BSTR];
    __shared__ int rowidx[128];
    __shared__ float Cst[8][16][20];
    const int t = threadIdx.x;
    const int w = t >> 5, lane = t & 31;
    const int wm = w & 3, wn = w >> 2;
    if (t < 128) {
        int p = t0 + t;
        rowidx[t] = g_rows[role * NROWS + (p < cnt ? p : cnt - 1)];
    }
    __syncthreads();
    wmma::fragment<wmma::accumulator, 16, 16, 16, float> acc[2][4];
#pragma unroll
    for (int i = 0; i < 2; i++)
#pragma unroll
        for (int j = 0; j < 4; j++) wmma::fill_fragment(acc[i][j], 0.f);
    const int ar = t >> 2, ac8 = (t & 3) * 8;
    const int br_ = t >> 4, bc8 = (t & 15) * 8;
    for (int k0 = 0; k0 < DOBS; k0 += 32) {
        *(uint4*)&Ash[ar][ac8]      = *(const uint4*)&g_obsnh[(size_t)rowidx[ar] * DOBS + k0 + ac8];
        *(uint4*)&Ash[ar + 64][ac8] = *(const uint4*)&g_obsnh[(size_t)rowidx[ar + 64] * DOBS + k0 + ac8];
        *(uint4*)&Asl[ar][ac8]      = *(const uint4*)&g_obsnl[(size_t)rowidx[ar] * DOBS + k0 + ac8];
        *(uint4*)&Asl[ar + 64][ac8] = *(const uint4*)&g_obsnl[(size_t)rowidx[ar + 64] * DOBS + k0 + ac8];
        *(uint4*)&Bsh[br_][bc8]      = *(const uint4*)&g_wr0h[((size_t)role * DOBS + k0 + br_) * 128 + bc8];
        *(uint4*)&Bsh[br_ + 16][bc8] = *(const uint4*)&g_wr0h[((size_t)role * DOBS + k0 + br_ + 16) * 128 + bc8];
        *(uint4*)&Bsl[br_][bc8]      = *(const uint4*)&g_wr0l[((size_t)role * DOBS + k0 + br_) * 128 + bc8];
        *(uint4*)&Bsl[br_ + 16][bc8] = *(const uint4*)&g_wr0l[((size_t)role * DOBS + k0 + br_ + 16) * 128 + bc8];
        __syncthreads();
#pragma unroll
        for (int ks = 0; ks < 2; ks++) {
            wmma::fragment<wmma::matrix_a, 16, 16, 16, bf16, wmma::row_major> fah[2], fal[2];
#pragma unroll
            for (int mi = 0; mi < 2; mi++) {
                wmma::load_matrix_sync(fah[mi], &Ash[wm * 32 + mi * 16][ks * 16], ASTR);
                wmma::load_matrix_sync(fal[mi], &Asl[wm * 32 + mi * 16][ks * 16], ASTR);
            }
#pragma unroll
            for (int ni = 0; ni < 4; ni++) {
                wmma::fragment<wmma::matrix_b, 16, 16, 16, bf16, wmma::row_major> fbh, fbl;
                wmma::load_matrix_sync(fbh, &Bsh[ks * 16][wn * 64 + ni * 16], BSTR);
                wmma::load_matrix_sync(fbl, &Bsl[ks * 16][wn * 64 + ni * 16], BSTR);
#pragma unroll
                for (int mi = 0; mi < 2; mi++) {
                    wmma::mma_sync(acc[mi][ni], fah[mi], fbh, acc[mi][ni]);
                    wmma::mma_sync(acc[mi][ni], fah[mi], fbl, acc[mi][ni]);
                    wmma::mma_sync(acc[mi][ni], fal[mi], fbh, acc[mi][ni]);
                }
            }
        }
        __syncthreads();
    }
    const int lr = lane & 15, lc = (lane >> 4) * 8;
#pragma unroll
    for (int mi = 0; mi < 2; mi++)
#pragma unroll
        for (int ni = 0; ni < 4; ni++) {
            wmma::store_matrix_sync(&Cst[w][0][0], acc[mi][ni], 20, wmma::mem_row_major);
            __syncwarp();
            int gr = wm * 32 + mi * 16 + lr;
            if (t0 + gr < cnt) {
                int g = rowidx[gr];
                int colb = wn * 64 + ni * 16 + lc;
#pragma unroll
                for (int j = 0; j < 8; j++) {
                    int c = colb + j;
                    float v = fmaxf(Cst[w][lr][lc + j] + br0[role * 128 + c], 0.f);
                    bf16 h = __float2bfloat16(v);
                    g_r0h[(size_t)g * 128 + c] = h;
                    g_r0l[(size_t)g * 128 + c] = __float2bfloat16(v - __bfloat162float(h));
                }
            }
            __syncwarp();
        }
}

// ---------------- route2 TC: e1hl = LN(pre2) + relu(r0 @ Wr1 + br1) -------
__global__ __launch_bounds__(256) void k_route2_tc(
    const float* __restrict__ l1s, const float* __restrict__ l1b,
    const float* __restrict__ br1)
{
    const int role = blockIdx.y;
    const int cnt = g_cnt[role];
    const int t0 = blockIdx.x * 128;
    if (t0 >= cnt) return;
    const int col0 = blockIdx.z * 128;
    __shared__ __align__(16) bf16 Ash[128][ASTR], Asl[128][ASTR];
    __shared__ __align__(16) bf16 Bsh[32][BSTR], Bsl[32][BSTR];
    __shared__ int rowidx[128];
    __shared__ float Cst[8][16][20];
    const int t = threadIdx.x;
    const int w = t >> 5, lane = t & 31;
    const int wm = w & 3, wn = w >> 2;
    if (t < 128) {
        int p = t0 + t;
        rowidx[t] = g_rows[role * NROWS + (p < cnt ? p : cnt - 1)];
    }
    __syncthreads();
    wmma::fragment<wmma::accumulator, 16, 16, 16, float> acc[2][4];
#pragma unroll
    for (int i = 0; i < 2; i++)
#pragma unroll
        for (int j = 0; j < 4; j++) wmma::fill_fragment(acc[i][j], 0.f);
    const int ar = t >> 2, ac8 = (t & 3) * 8;
    const int br_ = t >> 4, bc8 = (t & 15) * 8;
    for (int k0 = 0; k0 < 128; k0 += 32) {
        *(uint4*)&Ash[ar][ac8]      = *(const uint4*)&g_r0h[(size_t)rowidx[ar] * 128 + k0 + ac8];
        *(uint4*)&Ash[ar + 64][ac8] = *(const uint4*)&g_r0h[(size_t)rowidx[ar + 64] * 128 + k0 + ac8];
        *(uint4*)&Asl[ar][ac8]      = *(const uint4*)&g_r0l[(size_t)rowidx[ar] * 128 + k0 + ac8];
        *(uint4*)&Asl[ar + 64][ac8] = *(const uint4*)&g_r0l[(size_t)rowidx[ar + 64] * 128 + k0 + ac8];
        *(uint4*)&Bsh[br_][bc8]      = *(const uint4*)&g_wr1h[((size_t)role * 128 + k0 + br_) * HDIM + col0 + bc8];
        *(uint4*)&Bsh[br_ + 16][bc8] = *(const uint4*)&g_wr1h[((size_t)role * 128 + k0 + br_ + 16) * HDIM + col0 + bc8];
        *(uint4*)&Bsl[br_][bc8]      = *(const uint4*)&g_wr1l[((size_t)role * 128 + k0 + br_) * HDIM + col0 + bc8];
        *(uint4*)&Bsl[br_ + 16][bc8] = *(const uint4*)&g_wr1l[((size_t)role * 128 + k0 + br_ + 16) * HDIM + col0 + bc8];
        __syncthreads();
#pragma unroll
        for (int ks = 0; ks < 2; ks++) {
            wmma::fragment<wmma::matrix_a, 16, 16, 16, bf16, wmma::row_major> fah[2], fal[2];
#pragma unroll
            for (int mi = 0; mi < 2; mi++) {
                wmma::load_matrix_sync(fah[mi], &Ash[wm * 32 + mi * 16][ks * 16], ASTR);
                wmma::load_matrix_sync(fal[mi], &Asl[wm * 32 + mi * 16][ks * 16], ASTR);
            }
#pragma unroll
            for (int ni = 0; ni < 4; ni++) {
                wmma::fragment<wmma::matrix_b, 16, 16, 16, bf16, wmma::row_major> fbh, fbl;
                wmma::load_matrix_sync(fbh, &Bsh[ks * 16][wn * 64 + ni * 16], BSTR);
                wmma::load_matrix_sync(fbl, &Bsl[ks * 16][wn * 64 + ni * 16], BSTR);
#pragma unroll
                for (int mi = 0; mi < 2; mi++) {
                    wmma::mma_sync(acc[mi][ni], fah[mi], fbh, acc[mi][ni]);
                    wmma::mma_sync(acc[mi][ni], fah[mi], fbl, acc[mi][ni]);
                    wmma::mma_sync(acc[mi][ni], fal[mi], fbh, acc[mi][ni]);
                }
            }
        }
        __syncthreads();
    }
    const int lr = lane & 15, lc = (lane >> 4) * 8;
#pragma unroll
    for (int mi = 0; mi < 2; mi++)
#pragma unroll
        for (int ni = 0; ni < 4; ni++) {
            wmma::store_matrix_sync(&Cst[w][0][0], acc[mi][ni], 20, wmma::mem_row_major);
            __syncwarp();
            int gr = wm * 32 + mi * 16 + lr;
            if (t0 + gr < cnt) {
                int g = rowidx[gr];
                float m = g_mean[g], rs = g_rstd[g];
                int colb = col0 + wn * 64 + ni * 16 + lc;
#pragma unroll
                for (int j = 0; j < 8; j++) {
                    int c = colb + j;
                    float base = (g_pre2[(size_t)g * HDIM + c] - m) * rs * l1s[c] + l1b[c];
                    float v = fmaxf(Cst[w][lr][lc + j] + br1[role * HDIM + c], 0.f);
                    float y = base + v;
                    bf16 h = __float2bfloat16(y);
                    g_e1h[(size_t)g * HDIM + c] = h;
                    g_e1l[(size_t)g * HDIM + c] = __float2bfloat16(y - __bfloat162float(h));
                }
            }
            __syncwarp();
        }
}

// ---------------- heads: TC stage0 (512->64), fp32 stages 1-2 -------------
#define H0STR 68
__global__ __launch_bounds__(256) void k_heads(
    const float* __restrict__ bh0,
    const float* __restrict__ Wh1, const float* __restrict__ bh1,
    const float* __restrict__ Wh2, const float* __restrict__ bh2,
    const float* __restrict__ avail, float* __restrict__ outlog)
{
    const int role = blockIdx.y;
    const int cnt = g_cnt[role];
    const int t0 = blockIdx.x * 64;
    if (t0 >= cnt) return;
    extern __shared__ __align__(16) float sm[];
    float* h0s  = sm;                 // 64*68
    float* h1s  = sm + 4352;          // 64*33
    float* Wh1s = sm + 6464;          // 2048
    float* Wh2s = sm + 8512;          // 1024
    float* bh0s = sm + 9536;          // 64
    float* bh1s = sm + 9600;          // 32
    float* bh2s = sm + 9632;          // 32
    int* rowidx = (int*)(sm + 9664);  // 64
    bf16* Ash = (bf16*)(sm + 9728);   // 64*40
    bf16* Asl = (bf16*)(sm + 11008);  // 64*40
    bf16* Bsh = (bf16*)(sm + 12288);  // 32*72
    bf16* Bsl = (bf16*)(sm + 13440);  // 32*72
    const int t = threadIdx.x;
    const int w = t >> 5, lane = t & 31;
    const int wm = w & 3, wn = w >> 2;
    {
        const float4* s1 = (const float4*)(Wh1 + (size_t)role * 64 * 32);
#pragma unroll
        for (int i = 0; i < 2; i++) ((float4*)Wh1s)[t + i * 256] = s1[t + i * 256];
        ((float4*)Wh2s)[t] = ((const float4*)(Wh2 + (size_t)role * 32 * 32))[t];
        if (t < 64) bh0s[t] = bh0[role * 64 + t];
        if (t < 32) { bh1s[t] = bh1[role * 32 + t]; bh2s[t] = bh2[role * 32 + t]; }
        if (t < 64) {
            int p = t0 + t;
            rowidx[t] = g_rows[role * NROWS + (p < cnt ? p : cnt - 1)];
        }
    }
    __syncthreads();

    wmma::fragment<wmma::accumulator, 16, 16, 16, float> acc[2];
    wmma::fill_fragment(acc[0], 0.f);
    wmma::fill_fragment(acc[1], 0.f);
    const int ar = t >> 2, ac8 = (t & 3) * 8;
    const int br_ = t >> 3, bc8 = (t & 7) * 8;
    for (int k0 = 0; k0 < HDIM; k0 += 32) {
        *(uint4*)&Ash[ar * 40 + ac8] = *(const uint4*)&g_e1h[(size_t)rowidx[ar] * HDIM + k0 + ac8];
        *(uint4*)&Asl[ar * 40 + ac8] = *(const uint4*)&g_e1l[(size_t)rowidx[ar] * HDIM + k0 + ac8];
        *(uint4*)&Bsh[br_ * 72 + bc8] = *(const uint4*)&g_wh0h[((size_t)role * HDIM + k0 + br_) * 64 + bc8];
        *(uint4*)&Bsl[br_ * 72 + bc8] = *(const uint4*)&g_wh0l[((size_t)role * HDIM + k0 + br_) * 64 + bc8];
        __syncthreads();
#pragma unroll
        for (int ks = 0; ks < 2; ks++) {
            wmma::fragment<wmma::matrix_a, 16, 16, 16, bf16, wmma::row_major> fah, fal;
            wmma::load_matrix_sync(fah, &Ash[(wm * 16) * 40 + ks * 16], 40);
            wmma::load_matrix_sync(fal, &Asl[(wm * 16) * 40 + ks * 16], 40);
#pragma unroll
            for (int ni = 0; ni < 2; ni++) {
                wmma::fragment<wmma::matrix_b, 16, 16, 16, bf16, wmma::row_major> fbh, fbl;
                wmma::load_matrix_sync(fbh, &Bsh[ks * 16 * 72 + wn * 32 + ni * 16], 72);
                wmma::load_matrix_sync(fbl, &Bsl[ks * 16 * 72 + wn * 32 + ni * 16], 72);
                wmma::mma_sync(acc[ni], fah, fbh, acc[ni]);
                wmma::mma_sync(acc[ni], fah, fbl, acc[ni]);
                wmma::mma_sync(acc[ni], fal, fbh, acc[ni]);
            }
        }
        __syncthreads();
    }
#pragma unroll
    for (int ni = 0; ni < 2; ni++)
        wmma::store_matrix_sync(&h0s[(wm * 16) * H0STR + wn * 32 + ni * 16], acc[ni],
                                H0STR, wmma::mem_row_major);
    __syncthreads();
#pragma unroll
    for (int i = 0; i < 16; i++) {
        int idx = t + i * 256;
        int r = idx >> 6, c = idx & 63;
        h0s[r * H0STR + c] = fmaxf(h0s[r * H0STR + c] + bh0s[c], 0.f);
    }
    __syncthreads();

    const int c2 = t & 7, r2 = t >> 3;
    float acc1[2][4];
#pragma unroll
    for (int i = 0; i < 2; i++)
#pragma unroll
        for (int j = 0; j < 4; j++) acc1[i][j] = 0.f;
#pragma unroll
    for (int k = 0; k < 64; k++) {
        float a0 = h0s[(2 * r2) * H0STR + k];
        float a1 = h0s[(2 * r2 + 1) * H0STR + k];
#pragma unroll
        for (int j = 0; j < 4; j++) {
            float b = Wh1s[k * 32 + c2 + 8 * j];
            acc1[0][j] = fmaf(a0, b, acc1[0][j]);
            acc1[1][j] = fmaf(a1, b, acc1[1][j]);
        }
    }
#pragma unroll
    for (int i = 0; i < 2; i++)
#pragma unroll
        for (int j = 0; j < 4; j++) {
            int c = c2 + 8 * j;
            h1s[(2 * r2 + i) * 33 + c] = fmaxf(acc1[i][j] + bh1s[c], 0.f);
        }
    __syncthreads();

    float acc2[2][4];
#pragma unroll
    for (int i = 0; i < 2; i++)
#pragma unroll
        for (int j = 0; j < 4; j++) acc2[i][j] = 0.f;
#pragma unroll
    for (int k = 0; k < 32; k++) {
        float a0 = h1s[(2 * r2) * 33 + k];
        float a1 = h1s[(2 * r2 + 1) * 33 + k];
#pragma unroll
        for (int j = 0; j < 4; j++) {
            float b = Wh2s[k * 32 + c2 + 8 * j];
            acc2[0][j] = fmaf(a0, b, acc2[0][j]);
            acc2[1][j] = fmaf(a1, b, acc2[1][j]);
        }
    }
#pragma unroll
    for (int i = 0; i < 2; i++) {
        int rr = 2 * r2 + i;
        if (t0 + rr < cnt) {
            int g = rowidx[rr];
#pragma unroll
            for (int j = 0; j < 4; j++) {
                int c = c2 + 8 * j;
                float v = acc2[i][j] + bh2s[c];
                float av = avail[(size_t)g * NA + c];
                outlog[(size_t)g * NA + c] = (av > 0.5f) ? v : -1e10f;
            }
        }
    }
}

// ---------------- launch (R13 topology; LN kernels replaced by stats) ------
extern "C" void kernel_launch(void* const* d_in, const int* in_sizes, int n_in,
                              void* d_out, int out_size) {
    const float* rnn   = (const float*)d_in[0];
    const float* obs   = (const float*)d_in[1];
    const float* avail = (const float*)d_in[3];
    const int*   roles = (const int*)  d_in[4];
    const float* fns   = (const float*)d_in[5];
    const float* fnb   = (const float*)d_in[6];
    const float* W0    = (const float*)d_in[7];
    const float* b0    = (const float*)d_in[8];
    const float* l0s   = (const float*)d_in[9];
    const float* l0b   = (const float*)d_in[10];
    const float* W1    = (const float*)d_in[11];
    const float* b1    = (const float*)d_in[12];
    const float* l1s   = (const float*)d_in[13];
    const float* l1b   = (const float*)d_in[14];
    const float* Wr0   = (const float*)d_in[15];
    const float* br0   = (const float*)d_in[16];
    const float* Wr1   = (const float*)d_in[17];
    const float* br1   = (const float*)d_in[18];
    const float* Wh0   = (const float*)d_in[19];
    const float* bh0   = (const float*)d_in[20];
    const float* Wh1   = (const float*)d_in[21];
    const float* bh1   = (const float*)d_in[22];
    const float* Wh2   = (const float*)d_in[23];
    const float* bh2   = (const float*)d_in[24];
    float* out = (float*)d_out;

    void *p_obsnh, *p_obsnl, *p_w0h, *p_w0l, *p_w1h, *p_w1l, *p_pre, *p_pre2;
    cudaGetSymbolAddress(&p_obsnh, g_obsnh);
    cudaGetSymbolAddress(&p_obsnl, g_obsnl);
    cudaGetSymbolAddress(&p_w0h, g_w0h);
    cudaGetSymbolAddress(&p_w0l, g_w0l);
    cudaGetSymbolAddress(&p_w1h, g_w1h);
    cudaGetSymbolAddress(&p_w1l, g_w1l);
    cudaGetSymbolAddress(&p_pre, g_pre);
    cudaGetSymbolAddress(&p_pre2, g_pre2);

    const bf16* obsnh = (const bf16*)p_obsnh;
    const bf16* obsnl = (const bf16*)p_obsnl;
    const bf16* w0h = (const bf16*)p_w0h;
    const bf16* w0l = (const bf16*)p_w0l;
    const bf16* w1h = (const bf16*)p_w1h;
    const bf16* w1l = (const bf16*)p_w1l;
    float* pre = (float*)p_pre;
    float* pre2 = (float*)p_pre2;

    int logit_off = out_size - NROWS * NA;
    if (logit_off < 0) logit_off = 0;
    float* outlog = out + logit_off;

    const int HEADS_SMEM = 14592 * 4;
    cudaFuncSetAttribute(k_gemm_st, cudaFuncAttributeMaxDynamicSharedMemorySize, GEMM_SMEM);
    cudaFuncSetAttribute(k_gemm_lnA_st, cudaFuncAttributeMaxDynamicSharedMemorySize, GEMM_SMEM);
    cudaFuncSetAttribute(k_heads, cudaFuncAttributeMaxDynamicSharedMemorySize, HEADS_SMEM);

    // EXACTLY one side stream + 4 events (teardown-clean envelope).
    cudaStream_t s2;
    cudaStreamCreate(&s2);
    cudaEvent_t ev0, evSplit, evObs, evR1;
    cudaEventCreateWithFlags(&ev0, cudaEventDisableTiming);
    cudaEventCreateWithFlags(&evSplit, cudaEventDisableTiming);
    cudaEventCreateWithFlags(&evObs, cudaEventDisableTiming);
    cudaEventCreateWithFlags(&evR1, cudaEventDisableTiming);

    // fork
    cudaEventRecord(ev0, 0);
    cudaStreamWaitEvent(s2, ev0, 0);

    // s2: rnn passthrough + weight splits + bucketing
    if (logit_off > 0)
        k_copy4<<<(logit_off / 4 + 255) / 256, 256, 0, s2>>>((const float4*)rnn, (float4*)out, logit_off / 4);
    k_split_all<<<(N_SPLIT_TOT + 255) / 256, 256, 0, s2>>>(W0, W1, Wr0, Wr1, Wh0);
    cudaEventRecord(evSplit, s2);
    k_zero_cnt<<<1, 32, 0, s2>>>();
    k_bucket<<<NROWS / 256, 256, 0, s2>>>(roles);

    // main: obs LN (critical-path head)
    k_ln_obs<<<NROWS / 8, 256>>>(obs, fns, fnb);
    cudaEventRecord(evObs, 0);

    // s2: route1 — fully hidden under dense chain
    cudaStreamWaitEvent(s2, evObs, 0);
    k_route1_tc<<<dim3(NROWS / 128, NROLES), 256, 0, s2>>>(br0);
    cudaEventRecord(evR1, s2);

    // main: dense chain with fused LN stats (no k_ln512 passes)
    cudaStreamWaitEvent(0, evSplit, 0);
    k_gemm_st<<<dim3(NROWS / 128, HDIM / 128), 256, GEMM_SMEM>>>(
        obsnh, obsnl, w0h, w0l, b0, pre, DOBS);
    k_stats<<<NROWS / 256, 256>>>();
    k_gemm_lnA_st<<<dim3(NROWS / 128, HDIM / 128), 256, GEMM_SMEM>>>(
        pre, l0s, l0b, w1h, w1l, b1, pre2, HDIM);
    k_stats<<<NROWS / 256, 256>>>();

    // join: route2 reconstructs e1 = LN(pre2) + residual; heads consume e1hl
    cudaStreamWaitEvent(0, evR1, 0);
    k_route2_tc<<<dim3(NROWS / 128, NROLES, HDIM / 128), 256>>>(l1s, l1b, br1);
    k_heads<<<dim3(NROWS / 64, NROLES), 256, HEADS_SMEM>>>(bh0, Wh1, bh1, Wh2, bh2, avail, outlog);
}

// round 17
// speedup vs baseline: 1.0438x; 1.0438x over previous
#include <cuda_runtime.h>
#include <cuda_bf16.h>
#include <mma.h>

using namespace nvcuda;
typedef __nv_bfloat16 bf16;

#define NROWS 32768
#define DOBS 256
#define HDIM 512
#define NA 32
#define NROLES 6

// ---------------- cp.async helpers ----------------------------------------
__device__ __forceinline__ void cp16(void* sdst, const void* gsrc) {
    unsigned int d = (unsigned int)__cvta_generic_to_shared(sdst);
    asm volatile("cp.async.cg.shared.global [%0], [%1], 16;" :: "r"(d), "l"(gsrc));
}
#define CP_COMMIT() asm volatile("cp.async.commit_group;")
#define CP_WAIT(n)  asm volatile("cp.async.wait_group %0;" :: "n"(n))

// ---------------- scratch (device globals; no allocation allowed) ----------
__device__ __align__(256) bf16  g_obsnh[NROWS * DOBS];
__device__ __align__(256) bf16  g_obsnl[NROWS * DOBS];
__device__ __align__(256) bf16  g_w0h[DOBS * HDIM], g_w0l[DOBS * HDIM];
__device__ __align__(256) bf16  g_w1h[HDIM * HDIM], g_w1l[HDIM * HDIM];
__device__ __align__(256) bf16  g_wr0h[NROLES * DOBS * 128], g_wr0l[NROLES * DOBS * 128];
__device__ __align__(256) bf16  g_wr1h[NROLES * 128 * HDIM], g_wr1l[NROLES * 128 * HDIM];
__device__ __align__(256) bf16  g_wh0h[NROLES * HDIM * 64], g_wh0l[NROLES * HDIM * 64];
__device__ __align__(256) float g_pre[NROWS * HDIM];
__device__ __align__(256) bf16  g_e0h[NROWS * HDIM], g_e0l[NROWS * HDIM];
__device__ __align__(256) float g_e1[NROWS * HDIM];       // LN output (pre-residual)
__device__ __align__(256) bf16  g_e1h[NROWS * HDIM], g_e1l[NROWS * HDIM]; // post-residual
__device__ __align__(256) bf16  g_r0h[NROWS * 128], g_r0l[NROWS * 128];
__device__ int   g_rows[NROLES * NROWS];
__device__ int   g_cnt[NROLES];

// ---------------- small kernels -------------------------------------------
__global__ void k_copy4(const float4* __restrict__ src, float4* __restrict__ dst, int n4) {
    int i = blockIdx.x * blockDim.x + threadIdx.x;
    if (i < n4) dst[i] = src[i];
}

// warp-aggregated bucketing: one atomicAdd per (warp, distinct role)
__global__ void k_bucket(const int* __restrict__ role_ids) {
    int i = blockIdx.x * blockDim.x + threadIdx.x;
    int r = role_ids[i];
    unsigned mask = __match_any_sync(0xffffffffu, r);
    int lane = threadIdx.x & 31;
    int leader = __ffs(mask) - 1;
    int prefix = __popc(mask & ((1u << lane) - 1));
    int base = 0;
    if (lane == leader) base = atomicAdd(&g_cnt[r], __popc(mask));
    base = __shfl_sync(0xffffffffu, base, leader);
    g_rows[r * NROWS + base + prefix] = i;
}

// Fused split of all 5 weight tensors (also zeroes g_cnt: runs before k_bucket
// on the same stream).
#define N_W0  (DOBS * HDIM)
#define N_W1  (HDIM * HDIM)
#define N_WR0 (NROLES * DOBS * 128)
#define N_WR1 (NROLES * 128 * HDIM)
#define N_WH0 (NROLES * HDIM * 64)
#define N_SPLIT_TOT (N_W0 + N_W1 + N_WR0 + N_WR1 + N_WH0)
__global__ void k_split_all(const float* __restrict__ W0, const float* __restrict__ W1,
                            const float* __restrict__ Wr0, const float* __restrict__ Wr1,
                            const float* __restrict__ Wh0) {
    int i = blockIdx.x * blockDim.x + threadIdx.x;
    if (i < NROLES) g_cnt[i] = 0;
    if (i >= N_SPLIT_TOT) return;
    const float* src; bf16 *dh, *dl; int off;
    if (i < N_W0) { src = W0; dh = g_w0h; dl = g_w0l; off = i; }
    else if (i < N_W0 + N_W1) { src = W1; dh = g_w1h; dl = g_w1l; off = i - N_W0; }
    else if (i < N_W0 + N_W1 + N_WR0) { src = Wr0; dh = g_wr0h; dl = g_wr0l; off = i - N_W0 - N_W1; }
    else if (i < N_W0 + N_W1 + N_WR0 + N_WR1) { src = Wr1; dh = g_wr1h; dl = g_wr1l; off = i - N_W0 - N_W1 - N_WR0; }
    else { src = Wh0; dh = g_wh0h; dl = g_wh0l; off = i - N_W0 - N_W1 - N_WR0 - N_WR1; }
    float v = src[off];
    bf16 h = __float2bfloat16(v);
    dh[off] = h;
    dl[off] = __float2bfloat16(v - __bfloat162float(h));
}

// LayerNorm over obs (256), warp per row; writes bf16 hi/lo
__global__ void k_ln_obs(const float* __restrict__ obs, const float* __restrict__ sc,
                         const float* __restrict__ bi) {
    int warp = threadIdx.x >> 5, lane = threadIdx.x & 31;
    int row = blockIdx.x * 8 + warp;
    const float* src = obs + (size_t)row * DOBS;
    float x[8]; float s = 0.f, q = 0.f;
#pragma unroll
    for (int j = 0; j < 8; j++) { x[j] = src[lane + 32 * j]; s += x[j]; q += x[j] * x[j]; }
#pragma unroll
    for (int o = 16; o > 0; o >>= 1) {
        s += __shfl_xor_sync(0xffffffffu, s, o);
        q += __shfl_xor_sync(0xffffffffu, q, o);
    }
    float m = s * (1.f / DOBS);
    float v = q * (1.f / DOBS) - m * m;
    float rs = rsqrtf(v + 1e-5f);
#pragma unroll
    for (int j = 0; j < 8; j++) {
        int d = lane + 32 * j;
        float y = (x[j] - m) * rs * sc[d] + bi[d];
        size_t o = (size_t)row * DOBS + d;
        bf16 h = __float2bfloat16(y);
        g_obsnh[o] = h;
        g_obsnl[o] = __float2bfloat16(y - __bfloat162float(h));
    }
}

// bias + relu + LN(512). mode 0 -> bf16 hi/lo; mode 1 -> fp32
__global__ void k_ln512(const float* __restrict__ pre, const float* __restrict__ bias,
                        const float* __restrict__ g, const float* __restrict__ be,
                        float* __restrict__ outf, bf16* __restrict__ outh,
                        bf16* __restrict__ outl, int mode) {
    int warp = threadIdx.x >> 5, lane = threadIdx.x & 31;
    int row = blockIdx.x * 8 + warp;
    const float* src = pre + (size_t)row * HDIM;
    float x[16]; float s = 0.f, q = 0.f;
#pragma unroll
    for (int j = 0; j < 16; j++) {
        int d = lane + 32 * j;
        float v = fmaxf(src[d] + bias[d], 0.f);
        x[j] = v; s += v; q += v * v;
    }
#pragma unroll
    for (int o = 16; o > 0; o >>= 1) {
        s += __shfl_xor_sync(0xffffffffu, s, o);
        q += __shfl_xor_sync(0xffffffffu, q, o);
    }
    float m = s * (1.f / HDIM);
    float var = q * (1.f / HDIM) - m * m;
    float rs = rsqrtf(var + 1e-5f);
#pragma unroll
    for (int j = 0; j < 16; j++) {
        int d = lane + 32 * j;
        float y = (x[j] - m) * rs * g[d] + be[d];
        size_t o = (size_t)row * HDIM + d;
        if (mode == 0) {
            bf16 h = __float2bfloat16(y);
            outh[o] = h;
            outl[o] = __float2bfloat16(y - __bfloat162float(h));
        } else {
            outf[o] = y;
        }
    }
}

// ---------------- dense bf16x3 TC GEMM, cp.async double-buffered ----------
#define ASTR 40
#define BSTR 136
__global__ __launch_bounds__(256) void k_gemm_bf16(
    const bf16* __restrict__ Ah, const bf16* __restrict__ Al,
    const bf16* __restrict__ Wh, const bf16* __restrict__ Wl,
    float* __restrict__ out, int K)
{
    extern __shared__ __align__(16) char dsm[];
    const int A_SZ = 128 * ASTR * 2;
    const int B_SZ = 32 * BSTR * 2;
    const int STAGE = 2 * A_SZ + 2 * B_SZ;
    const int t = threadIdx.x;
    const int w = t >> 5;
    const int wm = w & 3, wn = w >> 2;
    const int row0 = blockIdx.x * 128, col0 = blockIdx.y * 128;

    wmma::fragment<wmma::accumulator, 16, 16, 16, float> acc[2][4];
#pragma unroll
    for (int i = 0; i < 2; i++)
#pragma unroll
        for (int j = 0; j < 4; j++) wmma::fill_fragment(acc[i][j], 0.f);

    const int ar = t >> 2, ac8 = (t & 3) * 8;
    const int br = t >> 4, bc8 = (t & 15) * 8;
    const int nk = K / 32;

    auto prefetch = [&](int s, int k0) {
        bf16* ah = (bf16*)(dsm + s * STAGE);
        bf16* al = (bf16*)(dsm + s * STAGE + A_SZ);
        bf16* bh = (bf16*)(dsm + s * STAGE + 2 * A_SZ);
        bf16* bl = (bf16*)(dsm + s * STAGE + 2 * A_SZ + B_SZ);
        cp16(&ah[ar * ASTR + ac8],        &Ah[(size_t)(row0 + ar) * K + k0 + ac8]);
        cp16(&ah[(ar + 64) * ASTR + ac8], &Ah[(size_t)(row0 + ar + 64) * K + k0 + ac8]);
        cp16(&al[ar * ASTR + ac8],        &Al[(size_t)(row0 + ar) * K + k0 + ac8]);
        cp16(&al[(ar + 64) * ASTR + ac8], &Al[(size_t)(row0 + ar + 64) * K + k0 + ac8]);
        cp16(&bh[br * BSTR + bc8],        &Wh[(size_t)(k0 + br) * HDIM + col0 + bc8]);
        cp16(&bh[(br + 16) * BSTR + bc8], &Wh[(size_t)(k0 + br + 16) * HDIM + col0 + bc8]);
        cp16(&bl[br * BSTR + bc8],        &Wl[(size_t)(k0 + br) * HDIM + col0 + bc8]);
        cp16(&bl[(br + 16) * BSTR + bc8], &Wl[(size_t)(k0 + br + 16) * HDIM + col0 + bc8]);
    };

    prefetch(0, 0);
    CP_COMMIT();
    for (int kt = 0; kt < nk; kt++) {
        int s = kt & 1;
        if (kt + 1 < nk) {
            prefetch((kt + 1) & 1, (kt + 1) * 32);
            CP_COMMIT();
            CP_WAIT(1);
        } else {
            CP_WAIT(0);
        }
        __syncthreads();
        bf16* ah = (bf16*)(dsm + s * STAGE);
        bf16* al = (bf16*)(dsm + s * STAGE + A_SZ);
        bf16* bh = (bf16*)(dsm + s * STAGE + 2 * A_SZ);
        bf16* bl = (bf16*)(dsm + s * STAGE + 2 * A_SZ + B_SZ);
#pragma unroll
        for (int ks = 0; ks < 2; ks++) {
            wmma::fragment<wmma::matrix_a, 16, 16, 16, bf16, wmma::row_major> fah[2], fal[2];
#pragma unroll
            for (int mi = 0; mi < 2; mi++) {
                wmma::load_matrix_sync(fah[mi], &ah[(wm * 32 + mi * 16) * ASTR + ks * 16], ASTR);
                wmma::load_matrix_sync(fal[mi], &al[(wm * 32 + mi * 16) * ASTR + ks * 16], ASTR);
            }
#pragma unroll
            for (int ni = 0; ni < 4; ni++) {
                wmma::fragment<wmma::matrix_b, 16, 16, 16, bf16, wmma::row_major> fbh, fbl;
                wmma::load_matrix_sync(fbh, &bh[ks * 16 * BSTR + wn * 64 + ni * 16], BSTR);
                wmma::load_matrix_sync(fbl, &bl[ks * 16 * BSTR + wn * 64 + ni * 16], BSTR);
#pragma unroll
                for (int mi = 0; mi < 2; mi++) {
                    wmma::mma_sync(acc[mi][ni], fah[mi], fbh, acc[mi][ni]);
                    wmma::mma_sync(acc[mi][ni], fah[mi], fbl, acc[mi][ni]);
                    wmma::mma_sync(acc[mi][ni], fal[mi], fbh, acc[mi][ni]);
                }
            }
        }
        __syncthreads();
    }
#pragma unroll
    for (int mi = 0; mi < 2; mi++)
#pragma unroll
        for (int ni = 0; ni < 4; ni++)
            wmma::store_matrix_sync(
                out + (size_t)(row0 + wm * 32 + mi * 16) * HDIM + col0 + wn * 64 + ni * 16,
                acc[mi][ni], HDIM, wmma::mem_row_major);
}

// ---------------- route1 TC: r0 = relu(obsn @ Wr0[role] + br0) ------------
__global__ __launch_bounds__(256) void k_route1_tc(const float* __restrict__ br0)
{
    const int role = blockIdx.y;
    const int cnt = g_cnt[role];
    const int t0 = blockIdx.x * 128;
    if (t0 >= cnt) return;
    __shared__ __align__(16) bf16 Ash[128][ASTR], Asl[128][ASTR];
    __shared__ __align__(16) bf16 Bsh[32][BSTR], Bsl[32][BSTR];
    __shared__ int rowidx[128];
    __shared__ float Cst[8][16][20];
    const int t = threadIdx.x;
    const int w = t >> 5, lane = t & 31;
    const int wm = w & 3, wn = w >> 2;
    if (t < 128) {
        int p = t0 + t;
        rowidx[t] = g_rows[role * NROWS + (p < cnt ? p : cnt - 1)];
    }
    __syncthreads();
    wmma::fragment<wmma::accumulator, 16, 16, 16, float> acc[2][4];
#pragma unroll
    for (int i = 0; i < 2; i++)
#pragma unroll
        for (int j = 0; j < 4; j++) wmma::fill_fragment(acc[i][j], 0.f);
    const int ar = t >> 2, ac8 = (t & 3) * 8;
    const int br_ = t >> 4, bc8 = (t & 15) * 8;
    for (int k0 = 0; k0 < DOBS; k0 += 32) {
        *(uint4*)&Ash[ar][ac8]      = *(const uint4*)&g_obsnh[(size_t)rowidx[ar] * DOBS + k0 + ac8];
        *(uint4*)&Ash[ar + 64][ac8] = *(const uint4*)&g_obsnh[(size_t)rowidx[ar + 64] * DOBS + k0 + ac8];
        *(uint4*)&Asl[ar][ac8]      = *(const uint4*)&g_obsnl[(size_t)rowidx[ar] * DOBS + k0 + ac8];
        *(uint4*)&Asl[ar + 64][ac8] = *(const uint4*)&g_obsnl[(size_t)rowidx[ar + 64] * DOBS + k0 + ac8];
        *(uint4*)&Bsh[br_][bc8]      = *(const uint4*)&g_wr0h[((size_t)role * DOBS + k0 + br_) * 128 + bc8];
        *(uint4*)&Bsh[br_ + 16][bc8] = *(const uint4*)&g_wr0h[((size_t)role * DOBS + k0 + br_ + 16) * 128 + bc8];
        *(uint4*)&Bsl[br_][bc8]      = *(const uint4*)&g_wr0l[((size_t)role * DOBS + k0 + br_) * 128 + bc8];
        *(uint4*)&Bsl[br_ + 16][bc8] = *(const uint4*)&g_wr0l[((size_t)role * DOBS + k0 + br_ + 16) * 128 + bc8];
        __syncthreads();
#pragma unroll
        for (int ks = 0; ks < 2; ks++) {
            wmma::fragment<wmma::matrix_a, 16, 16, 16, bf16, wmma::row_major> fah[2], fal[2];
#pragma unroll
            for (int mi = 0; mi < 2; mi++) {
                wmma::load_matrix_sync(fah[mi], &Ash[wm * 32 + mi * 16][ks * 16], ASTR);
                wmma::load_matrix_sync(fal[mi], &Asl[wm * 32 + mi * 16][ks * 16], ASTR);
            }
#pragma unroll
            for (int ni = 0; ni < 4; ni++) {
                wmma::fragment<wmma::matrix_b, 16, 16, 16, bf16, wmma::row_major> fbh, fbl;
                wmma::load_matrix_sync(fbh, &Bsh[ks * 16][wn * 64 + ni * 16], BSTR);
                wmma::load_matrix_sync(fbl, &Bsl[ks * 16][wn * 64 + ni * 16], BSTR);
#pragma unroll
                for (int mi = 0; mi < 2; mi++) {
                    wmma::mma_sync(acc[mi][ni], fah[mi], fbh, acc[mi][ni]);
                    wmma::mma_sync(acc[mi][ni], fah[mi], fbl, acc[mi][ni]);
                    wmma::mma_sync(acc[mi][ni], fal[mi], fbh, acc[mi][ni]);
                }
            }
        }
        __syncthreads();
    }
    const int lr = lane & 15, lc = (lane >> 4) * 8;
#pragma unroll
    for (int mi = 0; mi < 2; mi++)
#pragma unroll
        for (int ni = 0; ni < 4; ni++) {
            wmma::store_matrix_sync(&Cst[w][0][0], acc[mi][ni], 20, wmma::mem_row_major);
            __syncwarp();
            int gr = wm * 32 + mi * 16 + lr;
            if (t0 + gr < cnt) {
                int g = rowidx[gr];
                int colb = wn * 64 + ni * 16 + lc;
#pragma unroll
                for (int j = 0; j < 8; j++) {
                    int c = colb + j;
                    float v = fmaxf(Cst[w][lr][lc + j] + br0[role * 128 + c], 0.f);
                    bf16 h = __float2bfloat16(v);
                    g_r0h[(size_t)g * 128 + c] = h;
                    g_r0l[(size_t)g * 128 + c] = __float2bfloat16(v - __bfloat162float(h));
                }
            }
            __syncwarp();
        }
}

// ---------------- route2 TC: e1hl = e1 + relu(r0 @ Wr1[role] + br1) -------
__global__ __launch_bounds__(256) void k_route2_tc(const float* __restrict__ br1)
{
    const int role = blockIdx.y;
    const int cnt = g_cnt[role];
    const int t0 = blockIdx.x * 128;
    if (t0 >= cnt) return;
    const int col0 = blockIdx.z * 128;
    __shared__ __align__(16) bf16 Ash[128][ASTR], Asl[128][ASTR];
    __shared__ __align__(16) bf16 Bsh[32][BSTR], Bsl[32][BSTR];
    __shared__ int rowidx[128];
    __shared__ float Cst[8][16][20];
    const int t = threadIdx.x;
    const int w = t >> 5, lane = t & 31;
    const int wm = w & 3, wn = w >> 2;
    if (t < 128) {
        int p = t0 + t;
        rowidx[t] = g_rows[role * NROWS + (p < cnt ? p : cnt - 1)];
    }
    __syncthreads();
    wmma::fragment<wmma::accumulator, 16, 16, 16, float> acc[2][4];
#pragma unroll
    for (int i = 0; i < 2; i++)
#pragma unroll
        for (int j = 0; j < 4; j++) wmma::fill_fragment(acc[i][j], 0.f);
    const int ar = t >> 2, ac8 = (t & 3) * 8;
    const int br_ = t >> 4, bc8 = (t & 15) * 8;
    for (int k0 = 0; k0 < 128; k0 += 32) {
        *(uint4*)&Ash[ar][ac8]      = *(const uint4*)&g_r0h[(size_t)rowidx[ar] * 128 + k0 + ac8];
        *(uint4*)&Ash[ar + 64][ac8] = *(const uint4*)&g_r0h[(size_t)rowidx[ar + 64] * 128 + k0 + ac8];
        *(uint4*)&Asl[ar][ac8]      = *(const uint4*)&g_r0l[(size_t)rowidx[ar] * 128 + k0 + ac8];
        *(uint4*)&Asl[ar + 64][ac8] = *(const uint4*)&g_r0l[(size_t)rowidx[ar + 64] * 128 + k0 + ac8];
        *(uint4*)&Bsh[br_][bc8]      = *(const uint4*)&g_wr1h[((size_t)role * 128 + k0 + br_) * HDIM + col0 + bc8];
        *(uint4*)&Bsh[br_ + 16][bc8] = *(const uint4*)&g_wr1h[((size_t)role * 128 + k0 + br_ + 16) * HDIM + col0 + bc8];
        *(uint4*)&Bsl[br_][bc8]      = *(const uint4*)&g_wr1l[((size_t)role * 128 + k0 + br_) * HDIM + col0 + bc8];
        *(uint4*)&Bsl[br_ + 16][bc8] = *(const uint4*)&g_wr1l[((size_t)role * 128 + k0 + br_ + 16) * HDIM + col0 + bc8];
        __syncthreads();
#pragma unroll
        for (int ks = 0; ks < 2; ks++) {
            wmma::fragment<wmma::matrix_a, 16, 16, 16, bf16, wmma::row_major> fah[2], fal[2];
#pragma unroll
            for (int mi = 0; mi < 2; mi++) {
                wmma::load_matrix_sync(fah[mi], &Ash[wm * 32 + mi * 16][ks * 16], ASTR);
                wmma::load_matrix_sync(fal[mi], &Asl[wm * 32 + mi * 16][ks * 16], ASTR);
            }
#pragma unroll
            for (int ni = 0; ni < 4; ni++) {
                wmma::fragment<wmma::matrix_b, 16, 16, 16, bf16, wmma::row_major> fbh, fbl;
                wmma::load_matrix_sync(fbh, &Bsh[ks * 16][wn * 64 + ni * 16], BSTR);
                wmma::load_matrix_sync(fbl, &Bsl[ks * 16][wn * 64 + ni * 16], BSTR);
#pragma unroll
                for (int mi = 0; mi < 2; mi++) {
                    wmma::mma_sync(acc[mi][ni], fah[mi], fbh, acc[mi][ni]);
                    wmma::mma_sync(acc[mi][ni], fah[mi], fbl, acc[mi][ni]);
                    wmma::mma_sync(acc[mi][ni], fal[mi], fbh, acc[mi][ni]);
                }
            }
        }
        __syncthreads();
    }
    const int lr = lane & 15, lc = (lane >> 4) * 8;
#pragma unroll
    for (int mi = 0; mi < 2; mi++)
#pragma unroll
        for (int ni = 0; ni < 4; ni++) {
            wmma::store_matrix_sync(&Cst[w][0][0], acc[mi][ni], 20, wmma::mem_row_major);
            __syncwarp();
            int gr = wm * 32 + mi * 16 + lr;
            if (t0 + gr < cnt) {
                int g = rowidx[gr];
                int colb = col0 + wn * 64 + ni * 16 + lc;
#pragma unroll
                for (int j = 0; j < 8; j++) {
                    int c = colb + j;
                    float v = fmaxf(Cst[w][lr][lc + j] + br1[role * HDIM + c], 0.f);
                    float y = g_e1[(size_t)g * HDIM + c] + v;
                    bf16 h = __float2bfloat16(y);
                    g_e1h[(size_t)g * HDIM + c] = h;
                    g_e1l[(size_t)g * HDIM + c] = __float2bfloat16(y - __bfloat162float(h));
                }
            }
            __syncwarp();
        }
}

// ---------------- heads: TC stage0 (512->64), fp32 stages 1-2 -------------
#define H0STR 68
__global__ __launch_bounds__(256) void k_heads(
    const float* __restrict__ bh0,
    const float* __restrict__ Wh1, const float* __restrict__ bh1,
    const float* __restrict__ Wh2, const float* __restrict__ bh2,
    const float* __restrict__ avail, float* __restrict__ outlog)
{
    const int role = blockIdx.y;
    const int cnt = g_cnt[role];
    const int t0 = blockIdx.x * 64;
    if (t0 >= cnt) return;
    extern __shared__ __align__(16) float sm[];
    float* h0s  = sm;                 // 64*68
    float* h1s  = sm + 4352;          // 64*33
    float* Wh1s = sm + 6464;          // 2048
    float* Wh2s = sm + 8512;          // 1024
    float* bh0s = sm + 9536;          // 64
    float* bh1s = sm + 9600;          // 32
    float* bh2s = sm + 9632;          // 32
    int* rowidx = (int*)(sm + 9664);  // 64
    bf16* Ash = (bf16*)(sm + 9728);   // 64*40
    bf16* Asl = (bf16*)(sm + 11008);  // 64*40
    bf16* Bsh = (bf16*)(sm + 12288);  // 32*72
    bf16* Bsl = (bf16*)(sm + 13440);  // 32*72
    const int t = threadIdx.x;
    const int w = t >> 5, lane = t & 31;
    const int wm = w & 3, wn = w >> 2;
    {
        const float4* s1 = (const float4*)(Wh1 + (size_t)role * 64 * 32);
#pragma unroll
        for (int i = 0; i < 2; i++) ((float4*)Wh1s)[t + i * 256] = s1[t + i * 256];
        ((float4*)Wh2s)[t] = ((const float4*)(Wh2 + (size_t)role * 32 * 32))[t];
        if (t < 64) bh0s[t] = bh0[role * 64 + t];
        if (t < 32) { bh1s[t] = bh1[role * 32 + t]; bh2s[t] = bh2[role * 32 + t]; }
        if (t < 64) {
            int p = t0 + t;
            rowidx[t] = g_rows[role * NROWS + (p < cnt ? p : cnt - 1)];
        }
    }
    __syncthreads();

    wmma::fragment<wmma::accumulator, 16, 16, 16, float> acc[2];
    wmma::fill_fragment(acc[0], 0.f);
    wmma::fill_fragment(acc[1], 0.f);
    const int ar = t >> 2, ac8 = (t & 3) * 8;
    const int br_ = t >> 3, bc8 = (t & 7) * 8;
    for (int k0 = 0; k0 < HDIM; k0 += 32) {
        *(uint4*)&Ash[ar * 40 + ac8] = *(const uint4*)&g_e1h[(size_t)rowidx[ar] * HDIM + k0 + ac8];
        *(uint4*)&Asl[ar * 40 + ac8] = *(const uint4*)&g_e1l[(size_t)rowidx[ar] * HDIM + k0 + ac8];
        *(uint4*)&Bsh[br_ * 72 + bc8] = *(const uint4*)&g_wh0h[((size_t)role * HDIM + k0 + br_) * 64 + bc8];
        *(uint4*)&Bsl[br_ * 72 + bc8] = *(const uint4*)&g_wh0l[((size_t)role * HDIM + k0 + br_) * 64 + bc8];
        __syncthreads();
#pragma unroll
        for (int ks = 0; ks < 2; ks++) {
            wmma::fragment<wmma::matrix_a, 16, 16, 16, bf16, wmma::row_major> fah, fal;
            wmma::load_matrix_sync(fah, &Ash[(wm * 16) * 40 + ks * 16], 40);
            wmma::load_matrix_sync(fal, &Asl[(wm * 16) * 40 + ks * 16], 40);
#pragma unroll
            for (int ni = 0; ni < 2; ni++) {
                wmma::fragment<wmma::matrix_b, 16, 16, 16, bf16, wmma::row_major> fbh, fbl;
                wmma::load_matrix_sync(fbh, &Bsh[ks * 16 * 72 + wn * 32 + ni * 16], 72);
                wmma::load_matrix_sync(fbl, &Bsl[ks * 16 * 72 + wn * 32 + ni * 16], 72);
                wmma::mma_sync(acc[ni], fah, fbh, acc[ni]);
                wmma::mma_sync(acc[ni], fah, fbl, acc[ni]);
                wmma::mma_sync(acc[ni], fal, fbh, acc[ni]);
            }
        }
        __syncthreads();
    }
#pragma unroll
    for (int ni = 0; ni < 2; ni++)
        wmma::store_matrix_sync(&h0s[(wm * 16) * H0STR + wn * 32 + ni * 16], acc[ni],
                                H0STR, wmma::mem_row_major);
    __syncthreads();
#pragma unroll
    for (int i = 0; i < 16; i++) {
        int idx = t + i * 256;
        int r = idx >> 6, c = idx & 63;
        h0s[r * H0STR + c] = fmaxf(h0s[r * H0STR + c] + bh0s[c], 0.f);
    }
    __syncthreads();

    const int c2 = t & 7, r2 = t >> 3;
    float acc1[2][4];
#pragma unroll
    for (int i = 0; i < 2; i++)
#pragma unroll
        for (int j = 0; j < 4; j++) acc1[i][j] = 0.f;
#pragma unroll
    for (int k = 0; k < 64; k++) {
        float a0 = h0s[(2 * r2) * H0STR + k];
        float a1 = h0s[(2 * r2 + 1) * H0STR + k];
#pragma unroll
        for (int j = 0; j < 4; j++) {
            float b = Wh1s[k * 32 + c2 + 8 * j];
            acc1[0][j] = fmaf(a0, b, acc1[0][j]);
            acc1[1][j] = fmaf(a1, b, acc1[1][j]);
        }
    }
#pragma unroll
    for (int i = 0; i < 2; i++)
#pragma unroll
        for (int j = 0; j < 4; j++) {
            int c = c2 + 8 * j;
            h1s[(2 * r2 + i) * 33 + c] = fmaxf(acc1[i][j] + bh1s[c], 0.f);
        }
    __syncthreads();

    float acc2[2][4];
#pragma unroll
    for (int i = 0; i < 2; i++)
#pragma unroll
        for (int j = 0; j < 4; j++) acc2[i][j] = 0.f;
#pragma unroll
    for (int k = 0; k < 32; k++) {
        float a0 = h1s[(2 * r2) * 33 + k];
        float a1 = h1s[(2 * r2 + 1) * 33 + k];
#pragma unroll
        for (int j = 0; j < 4; j++) {
            float b = Wh2s[k * 32 + c2 + 8 * j];
            acc2[0][j] = fmaf(a0, b, acc2[0][j]);
            acc2[1][j] = fmaf(a1, b, acc2[1][j]);
        }
    }
#pragma unroll
    for (int i = 0; i < 2; i++) {
        int rr = 2 * r2 + i;
        if (t0 + rr < cnt) {
            int g = rowidx[rr];
#pragma unroll
            for (int j = 0; j < 4; j++) {
                int c = c2 + 8 * j;
                float v = acc2[i][j] + bh2s[c];
                float av = avail[(size_t)g * NA + c];
                outlog[(size_t)g * NA + c] = (av > 0.5f) ? v : -1e10f;
            }
        }
    }
}

// ---------------- launch (R13 champion topology) ---------------------------
extern "C" void kernel_launch(void* const* d_in, const int* in_sizes, int n_in,
                              void* d_out, int out_size) {
    const float* rnn   = (const float*)d_in[0];
    const float* obs   = (const float*)d_in[1];
    const float* avail = (const float*)d_in[3];
    const int*   roles = (const int*)  d_in[4];
    const float* fns   = (const float*)d_in[5];
    const float* fnb   = (const float*)d_in[6];
    const float* W0    = (const float*)d_in[7];
    const float* b0    = (const float*)d_in[8];
    const float* l0s   = (const float*)d_in[9];
    const float* l0b   = (const float*)d_in[10];
    const float* W1    = (const float*)d_in[11];
    const float* b1    = (const float*)d_in[12];
    const float* l1s   = (const float*)d_in[13];
    const float* l1b   = (const float*)d_in[14];
    const float* Wr0   = (const float*)d_in[15];
    const float* br0   = (const float*)d_in[16];
    const float* Wr1   = (const float*)d_in[17];
    const float* br1   = (const float*)d_in[18];
    const float* Wh0   = (const float*)d_in[19];
    const float* bh0   = (const float*)d_in[20];
    const float* Wh1   = (const float*)d_in[21];
    const float* bh1   = (const float*)d_in[22];
    const float* Wh2   = (const float*)d_in[23];
    const float* bh2   = (const float*)d_in[24];
    float* out = (float*)d_out;

    void *p_obsnh, *p_obsnl, *p_w0h, *p_w0l, *p_w1h, *p_w1l;
    void *p_pre, *p_e0h, *p_e0l, *p_e1;
    cudaGetSymbolAddress(&p_obsnh, g_obsnh);
    cudaGetSymbolAddress(&p_obsnl, g_obsnl);
    cudaGetSymbolAddress(&p_w0h, g_w0h);
    cudaGetSymbolAddress(&p_w0l, g_w0l);
    cudaGetSymbolAddress(&p_w1h, g_w1h);
    cudaGetSymbolAddress(&p_w1l, g_w1l);
    cudaGetSymbolAddress(&p_pre, g_pre);
    cudaGetSymbolAddress(&p_e0h, g_e0h);
    cudaGetSymbolAddress(&p_e0l, g_e0l);
    cudaGetSymbolAddress(&p_e1, g_e1);

    const bf16* obsnh = (const bf16*)p_obsnh;
    const bf16* obsnl = (const bf16*)p_obsnl;
    const bf16* w0h = (const bf16*)p_w0h;
    const bf16* w0l = (const bf16*)p_w0l;
    const bf16* w1h = (const bf16*)p_w1h;
    const bf16* w1l = (const bf16*)p_w1l;
    float* pre = (float*)p_pre;
    bf16* e0h = (bf16*)p_e0h;
    bf16* e0l = (bf16*)p_e0l;
    float* e1 = (float*)p_e1;

    int logit_off = out_size - NROWS * NA;
    if (logit_off < 0) logit_off = 0;
    float* outlog = out + logit_off;

    const int GEMM_SMEM = 2 * (2 * 128 * ASTR * 2 + 2 * 32 * BSTR * 2);
    const int HEADS_SMEM = 14592 * 4;
    cudaFuncSetAttribute(k_gemm_bf16, cudaFuncAttributeMaxDynamicSharedMemorySize, GEMM_SMEM);
    cudaFuncSetAttribute(k_heads, cudaFuncAttributeMaxDynamicSharedMemorySize, HEADS_SMEM);

    // EXACTLY one side stream + 4 events (teardown-clean envelope).
    cudaStream_t s2;
    cudaStreamCreate(&s2);
    cudaEvent_t ev0, evSplit, evObs, evR1;
    cudaEventCreateWithFlags(&ev0, cudaEventDisableTiming);
    cudaEventCreateWithFlags(&evSplit, cudaEventDisableTiming);
    cudaEventCreateWithFlags(&evObs, cudaEventDisableTiming);
    cudaEventCreateWithFlags(&evR1, cudaEventDisableTiming);

    // fork
    cudaEventRecord(ev0, 0);
    cudaStreamWaitEvent(s2, ev0, 0);

    // s2: rnn passthrough + weight splits (zeroes g_cnt) + bucketing
    if (logit_off > 0)
        k_copy4<<<(logit_off / 4 + 255) / 256, 256, 0, s2>>>((const float4*)rnn, (float4*)out, logit_off / 4);
    k_split_all<<<(N_SPLIT_TOT + 255) / 256, 256, 0, s2>>>(W0, W1, Wr0, Wr1, Wh0);
    cudaEventRecord(evSplit, s2);
    k_bucket<<<NROWS / 256, 256, 0, s2>>>(roles);

    // main: obs LN (critical-path head)
    k_ln_obs<<<NROWS / 8, 256>>>(obs, fns, fnb);
    cudaEventRecord(evObs, 0);

    // s2: route1 (needs obsn + buckets + Wr0) — fully hidden under dense chain
    cudaStreamWaitEvent(s2, evObs, 0);
    k_route1_tc<<<dim3(NROWS / 128, NROLES), 256, 0, s2>>>(br0);
    cudaEventRecord(evR1, s2);

    // main: full dense chain (proven shape)
    cudaStreamWaitEvent(0, evSplit, 0);
    k_gemm_bf16<<<dim3(NROWS / 128, HDIM / 128), 256, GEMM_SMEM>>>(
        obsnh, obsnl, w0h, w0l, pre, DOBS);
    k_ln512<<<NROWS / 8, 256>>>(pre, b0, l0s, l0b, e1, e0h, e0l, 0);
    k_gemm_bf16<<<dim3(NROWS / 128, HDIM / 128), 256, GEMM_SMEM>>>(
        e0h, e0l, w1h, w1l, pre, HDIM);
    k_ln512<<<NROWS / 8, 256>>>(pre, b1, l1s, l1b, e1, e0h, e0l, 1);

    // join: route2 needs r0 + e1
    cudaStreamWaitEvent(0, evR1, 0);
    k_route2_tc<<<dim3(NROWS / 128, NROLES, HDIM / 128), 256>>>(br1);
    k_heads<<<dim3(NROWS / 64, NROLES), 256, HEADS_SMEM>>>(bh0, Wh1, bh1, Wh2, bh2, avail, outlog);
}